// round 15
// baseline (speedup 1.0000x reference)
#include <cuda_runtime.h>
#include <cuda_fp16.h>
#include <cstdint>

#define Bsz 256
#define Lsz 500
#define Dsz 3
#define Csz 32
#define Isz 35
#define Hsz 512
#define Msz 5
#define Osz 15
#define Jsz 35
#define NC  50
#define LC  10
#define BH  (Bsz*Hsz)   /* 131072 */
#define BL  (Bsz*Lsz)   /* 128000 */
#define NSL 4           /* h slices */
#define HS  (Hsz/NSL)   /* 128 */
#define BT  128         /* b tile */
#define NBT (Bsz/BT)    /* 2 */
#define NT  512

/* ---- k_sums v4 (3x-fp16 HMMA encoder) ---- */
#define KP   24          /* half2-k rows (K = 48, 35 used) */
#define XROW 28          /* xs row stride (u32) -> banks (-4rq+kl) distinct */
#define WROW 136         /* ws row stride (u32) -> banks (8kl+rq) distinct */
#define WSZ  (KP*WROW)   /* 3264 u32 per plane */
#define XSZ  (128*XROW)  /* 3584 u32 per plane */
#define SMS_TOT ((4*WSZ + 4*XSZ) * 4)   /* 109568 B */

/* ---- k_all v4 smem (R14 known-good) ---- */
#define HROW 68
#define HBUF (128*HROW)
#define VBUF (64*40)
#define SM_HS 0
#define SM_VS (2*HBUF*4)
#define SMA_TOT (SM_VS + 2*VBUF*4)   /* 90112 B */

extern __shared__ __align__(16) char dyn_smem[];

// Scratch
__device__ __align__(16) float  g_S[(size_t)NC * BH];
__device__ __align__(16) float  g_P[(size_t)NC * BH];
__device__ __align__(16) float  g_part[(size_t)NSL * BL * 40];
__device__ __align__(16) __half g_c16[(size_t)Lsz * BH];

using u64 = unsigned long long;

__device__ __forceinline__ void barrier0() { asm volatile("barrier.sync 0;" ::: "memory"); }

// m16n8k16 fp16 HMMA, fp32 accumulate (fragment layout validated R10/R11/R14)
__device__ __forceinline__ void mma_f16(float d[4],
                                        unsigned a0, unsigned a1, unsigned a2, unsigned a3,
                                        unsigned b0, unsigned b1) {
    asm volatile(
        "mma.sync.aligned.m16n8k16.row.col.f32.f16.f16.f32 "
        "{%0,%1,%2,%3}, {%4,%5,%6,%7}, {%8,%9}, {%0,%1,%2,%3};"
        : "+f"(d[0]), "+f"(d[1]), "+f"(d[2]), "+f"(d[3])
        : "r"(a0), "r"(a1), "r"(a2), "r"(a3), "r"(b0), "r"(b1));
}

__device__ __forceinline__ void fsplit(float v, float& hi, float& lo) {
    __half h = __float2half_rn(v);
    hi = __half2float(h);
    lo = v - hi;
}
__device__ __forceinline__ unsigned packh2(float a, float b) {
    __half2 h = __floats2half2_rn(a, b);
    return *(unsigned*)&h;
}

// ---------------------------------------------------------------------------
// k_sums v4: encoder via 3-pass fp16 HMMA (error-compensated).
// Block = (btile*NSL + hslice, chunk), 512 threads = 16 warps:
//   sb = wid&7 (16-row b strip), nh = wid>>3 (64-h half).
// Per warp-step: D[16b x 64h] over K=48, 8 n-tiles x 3 kc x 3 passes = 72 mma.
// S chunk sums accumulate in fp32 fragment regs; c16 stored per step.
// W/x staged as hi/lo half2-k planes, double-buffered, loads issued early.
// ---------------------------------------------------------------------------
__global__ void __launch_bounds__(NT) k_sums(const float* __restrict__ inp,
                                             const float* __restrict__ zz,
                                             const float* __restrict__ W)
{
    unsigned* sm = (unsigned*)dyn_smem;
    unsigned* wsH[2] = { sm,           sm + WSZ };
    unsigned* wsL[2] = { sm + 2*WSZ,   sm + 3*WSZ };
    unsigned* xsH[2] = { sm + 4*WSZ,           sm + 4*WSZ + XSZ };
    unsigned* xsL[2] = { sm + 4*WSZ + 2*XSZ,   sm + 4*WSZ + 3*XSZ };

    const int tid = threadIdx.x;
    const int wid = tid >> 5, lane = tid & 31;
    const int b0  = (blockIdx.x / NSL) * BT;
    const int h0  = (blockIdx.x % NSL) * HS;
    const int k   = blockIdx.y;
    const int l0  = k * LC;
    const int sb  = wid & 7, nh = wid >> 3;
    const int rq  = lane >> 2, kl = lane & 3;
    const int rb  = sb * 16 + rq;

    // staging destination descriptors (loop-invariant)
    int wk2[6], wh_[6], xb[6], xk2[6];
#pragma unroll
    for (int q = 0; q < 6; q++) {
        int wi = tid + NT * q;            // 0..3071 = 24 k2 x 128 h
        wk2[q] = wi >> 7; wh_[q] = wi & 127;
        int xi = tid + NT * q;            // 0..3071 = 128 b x 24 k2
        xb[q] = xi / KP; xk2[q] = xi % KP;
    }

    auto xval = [&](int b, int l, int i) -> float {
        if (i < Dsz) return inp[(size_t)(b0 + b) * (Lsz * Dsz) + (size_t)l * Dsz + i];
        if (i < Isz) return zz [(size_t)(b0 + b) * (Lsz * Csz) + (size_t)l * Csz + (i - Dsz)];
        return 0.0f;
    };
    auto load_W = [&](int l, unsigned wh[6], unsigned wl[6]) {
        const float* Wl = W + (size_t)l * (Isz * Hsz) + h0;
#pragma unroll
        for (int q = 0; q < 6; q++) {
            int i0 = 2 * wk2[q], i1 = i0 + 1;
            float v0 = (i0 < Isz) ? Wl[(size_t)i0 * Hsz + wh_[q]] : 0.0f;
            float v1 = (i1 < Isz) ? Wl[(size_t)i1 * Hsz + wh_[q]] : 0.0f;
            float h0f, l0f, h1f, l1f;
            fsplit(v0, h0f, l0f); fsplit(v1, h1f, l1f);
            wh[q] = packh2(h0f, h1f); wl[q] = packh2(l0f, l1f);
        }
    };
    auto load_X = [&](int l, unsigned xh[6], unsigned xl[6]) {
#pragma unroll
        for (int q = 0; q < 6; q++) {
            int i0 = 2 * xk2[q], i1 = i0 + 1;
            float v0 = xval(xb[q], l, i0);
            float v1 = xval(xb[q], l, i1);
            float h0f, l0f, h1f, l1f;
            fsplit(v0, h0f, l0f); fsplit(v1, h1f, l1f);
            xh[q] = packh2(h0f, h1f); xl[q] = packh2(l0f, l1f);
        }
    };
    auto store_stage = [&](int buf, const unsigned wh[6], const unsigned wl[6],
                           const unsigned xh[6], const unsigned xl[6]) {
#pragma unroll
        for (int q = 0; q < 6; q++) {
            unsigned wd = (unsigned)(wk2[q] * WROW + wh_[q]);
            unsigned xd = (unsigned)(xb[q] * XROW + xk2[q]);
            wsH[buf][wd] = wh[q]; wsL[buf][wd] = wl[q];
            xsH[buf][xd] = xh[q]; xsL[buf][xd] = xl[q];
        }
    };

    // S fragment accumulators (fp32)
    float S[8][4];
#pragma unroll
    for (int n = 0; n < 8; n++)
#pragma unroll
        for (int u = 0; u < 4; u++) S[n][u] = 0.0f;

    // prologue: stage step l0 into buffer 0
    {
        unsigned wh[6], wl[6], xh[6], xl[6];
        load_W(l0, wh, wl); load_X(l0, xh, xl);
        store_stage(0, wh, wl, xh, xl);
    }
    barrier0();

    for (int t = 0; t < LC; t++) {
        const int l = l0 + t;
        const int cur = t & 1, nxt = cur ^ 1;

        // issue next-step loads early (latency hidden under mma)
        unsigned whN[6], wlN[6], xhN[6], xlN[6];
        if (t + 1 < LC) { load_W(l + 1, whN, wlN); load_X(l + 1, xhN, xlN); }

        // ---- 3-pass HMMA: c = xh@wh + xh@wl + xl@wh
        float d[8][4];
#pragma unroll
        for (int n = 0; n < 8; n++)
#pragma unroll
            for (int u = 0; u < 4; u++) d[n][u] = 0.0f;

        const unsigned* xhc = xsH[cur]; const unsigned* xlc = xsL[cur];
        const unsigned* whc = wsH[cur]; const unsigned* wlc = wsL[cur];
#pragma unroll
        for (int kc = 0; kc < 3; kc++) {
            const int k2b = kc * 8;
            unsigned aH0 = xhc[rb * XROW + k2b + kl];
            unsigned aH1 = xhc[(rb + 8) * XROW + k2b + kl];
            unsigned aH2 = xhc[rb * XROW + k2b + 4 + kl];
            unsigned aH3 = xhc[(rb + 8) * XROW + k2b + 4 + kl];
            unsigned aL0 = xlc[rb * XROW + k2b + kl];
            unsigned aL1 = xlc[(rb + 8) * XROW + k2b + kl];
            unsigned aL2 = xlc[rb * XROW + k2b + 4 + kl];
            unsigned aL3 = xlc[(rb + 8) * XROW + k2b + 4 + kl];
#pragma unroll
            for (int n = 0; n < 8; n++) {
                const int col = nh * 64 + n * 8 + rq;
                unsigned bH0 = whc[(k2b + kl) * WROW + col];
                unsigned bH1 = whc[(k2b + 4 + kl) * WROW + col];
                unsigned bL0 = wlc[(k2b + kl) * WROW + col];
                unsigned bL1 = wlc[(k2b + 4 + kl) * WROW + col];
                mma_f16(d[n], aH0, aH1, aH2, aH3, bH0, bH1);
                mma_f16(d[n], aH0, aH1, aH2, aH3, bL0, bL1);
                mma_f16(d[n], aL0, aL1, aL2, aL3, bH0, bH1);
            }
        }

        // ---- epilogue: S += c; store c16[l]
        {
            __half* c0 = g_c16 + ((size_t)l * Bsz + b0 + rb) * Hsz + h0;
            __half* c1 = g_c16 + ((size_t)l * Bsz + b0 + rb + 8) * Hsz + h0;
#pragma unroll
            for (int n = 0; n < 8; n++) {
#pragma unroll
                for (int u = 0; u < 4; u++) S[n][u] += d[n][u];
                const int hc = nh * 64 + n * 8 + 2 * kl;
                __half2 p0 = __floats2half2_rn(d[n][0], d[n][1]);
                __half2 p1 = __floats2half2_rn(d[n][2], d[n][3]);
                *(__half2*)&c0[hc] = p0;
                *(__half2*)&c1[hc] = p1;
            }
        }

        if (t + 1 < LC) store_stage(nxt, whN, wlN, xhN, xlN);
        barrier0();
    }

    // final S store (fragment positions -> [b][h] layout)
    {
        float* s0 = g_S + (size_t)k * BH + (size_t)(b0 + rb) * Hsz + h0;
        float* s1 = g_S + (size_t)k * BH + (size_t)(b0 + rb + 8) * Hsz + h0;
#pragma unroll
        for (int n = 0; n < 8; n++) {
            const int hc = nh * 64 + n * 8 + 2 * kl;
            *(float2*)&s0[hc] = make_float2(S[n][0], S[n][1]);
            *(float2*)&s1[hc] = make_float2(S[n][2], S[n][3]);
        }
    }
}

__global__ void k_scan(const float* __restrict__ benc)
{
    const int idx = blockIdx.x * 256 + threadIdx.x;
    float run = benc[idx & (Hsz - 1)];
#pragma unroll 5
    for (int k = 0; k < NC; k++) {
        g_P[(size_t)k * BH + idx] = run;
        run += g_S[(size_t)k * BH + idx];
    }
}

// ---------------------------------------------------------------------------
// k_all v4: R14 known-good warp-specialized kernel (UNTOUCHED).
// ---------------------------------------------------------------------------
__global__ void __launch_bounds__(NT) k_all(const float* __restrict__ Vmu,
                                            const float* __restrict__ Vsg,
                                            const float* __restrict__ Vpi)
{
    unsigned* hsb = (unsigned*)(dyn_smem + SM_HS);   // [2][128][HROW]
    unsigned* vsb = (unsigned*)(dyn_smem + SM_VS);   // [2][64][40]

    const int tid = threadIdx.x;
    const int wid = tid >> 5, lane = tid & 31;
    const int b0  = (blockIdx.x / NSL) * BT;
    const int s   = blockIdx.x % NSL;
    const int h0  = s * HS;
    const int l0  = blockIdx.y * LC;

    if (wid < 8) {
        // ================= MMA role =================
        const int sb = wid;
        const int rq = lane >> 2, kl = lane & 3;
        const int rb = sb * 16 + rq;

        unsigned vq[10], vdst[10];
#pragma unroll
        for (int q = 0; q < 10; q++) {
            int u = tid + 256 * q;
            int h2 = u / 40, jc = u % 40;
            unsigned tag, off;
            if (jc < 15)      { tag = 0u; off = (h0 + 2 * h2) * Osz + jc; }
            else if (jc < 30) { tag = 1u; off = (h0 + 2 * h2) * Osz + (jc - 15); }
            else if (jc < 35) { tag = 2u; off = (h0 + 2 * h2) * Msz + (jc - 30); }
            else              { tag = 3u; off = 0; }
            vq[q] = (tag << 30) | off;
            vdst[q] = (unsigned)(h2 * 40 + jc);
        }
        auto load_V = [&](int l, unsigned vreg[10]) {
            const size_t lmu = (size_t)l * (Hsz * Osz);
            const size_t lpi = (size_t)l * (Hsz * Msz);
#pragma unroll
            for (int q = 0; q < 10; q++) {
                unsigned tag = vq[q] >> 30, off = vq[q] & 0x3FFFFFFFu;
                float v0 = 0.0f, v1 = 0.0f;
                if (tag == 0u)      { v0 = Vmu[lmu + off]; v1 = Vmu[lmu + off + Osz]; }
                else if (tag == 1u) { v0 = Vsg[lmu + off]; v1 = Vsg[lmu + off + Osz]; }
                else if (tag == 2u) { v0 = Vpi[lpi + off]; v1 = Vpi[lpi + off + Msz]; }
                __half2 h2v = __floats2half2_rn(v0, v1);
                vreg[q] = *(unsigned*)&h2v;
            }
        };

        {
            unsigned v0[10];
            load_V(l0, v0);
#pragma unroll
            for (int q = 0; q < 10; q++) vsb[vdst[q]] = v0[q];
        }
        barrier0();

        for (int t = 0; t < LC; t++) {
            const int l = l0 + t;
            const int cur = t & 1, nxt = cur ^ 1;
            const unsigned* hsc = hsb + cur * HBUF;
            const unsigned* vsc = vsb + cur * VBUF;

            unsigned vreg[10];
            if (t + 1 < LC) load_V(l + 1, vreg);

            float d[5][4];
#pragma unroll
            for (int n = 0; n < 5; n++)
#pragma unroll
                for (int u = 0; u < 4; u++) d[n][u] = 0.0f;

#pragma unroll
            for (int kc = 0; kc < 8; kc++) {
                const int k0h = kc * 8;
                unsigned a0 = hsc[rb * HROW + k0h + kl];
                unsigned a1 = hsc[(rb + 8) * HROW + k0h + kl];
                unsigned a2 = hsc[rb * HROW + k0h + 4 + kl];
                unsigned a3 = hsc[(rb + 8) * HROW + k0h + 4 + kl];
#pragma unroll
                for (int n = 0; n < 5; n++) {
                    unsigned bf0 = vsc[(k0h + kl) * 40 + n * 8 + rq];
                    unsigned bf1 = vsc[(k0h + 4 + kl) * 40 + n * 8 + rq];
                    mma_f16(d[n], a0, a1, a2, a3, bf0, bf1);
                }
            }

            {
                float* d0 = g_part + ((size_t)s * BL + (size_t)l * Bsz + (b0 + rb)) * 40;
                float* d1 = g_part + ((size_t)s * BL + (size_t)l * Bsz + (b0 + rb + 8)) * 40;
#pragma unroll
                for (int n = 0; n < 5; n++) {
                    const int j = n * 8 + 2 * kl;
                    *(float2*)&d0[j] = make_float2(d[n][0], d[n][1]);
                    *(float2*)&d1[j] = make_float2(d[n][2], d[n][3]);
                }
            }

            if (t + 1 < LC) {
                unsigned* vsn = vsb + nxt * VBUF;
#pragma unroll
                for (int q = 0; q < 10; q++) vsn[vdst[q]] = vreg[q];
            }
            barrier0();
        }
    } else {
        // ================= STATE role =================
        const int stid = tid - 256;
        const int b    = stid >> 1;
        const int shf  = stid & 1;
        const unsigned hcol = (unsigned)(b * HROW + shf * 32);

        u64 acc[32];
        {
            const float* P = g_P + (size_t)blockIdx.y * BH
                           + (size_t)(b0 + b) * Hsz + h0 + shf * 64;
#pragma unroll
            for (int j2 = 0; j2 < 32; j2++) {
                float2 v = *(const float2*)&P[2 * j2];
                acc[j2] = *(const u64*)&v;
            }
        }
        {
            unsigned* hsn = hsb;
#pragma unroll
            for (int j2 = 0; j2 < 32; j2++) {
                float2 v = *(float2*)&acc[j2];
                __half2 h2v = __floats2half2_rn(fmaxf(v.x, 0.0f), fmaxf(v.y, 0.0f));
                hsn[hcol + j2] = *(unsigned*)&h2v;
            }
        }
        uint4 c4[8];
        {
            const uint4* src = (const uint4*)(g_c16
                + ((size_t)l0 * Bsz + b0 + b) * Hsz + h0 + shf * 64);
#pragma unroll
            for (int q = 0; q < 8; q++) c4[q] = src[q];
        }
        barrier0();

        for (int t = 0; t < LC; t++) {
            const int nxt = (t & 1) ^ 1;

#pragma unroll
            for (int q = 0; q < 8; q++) {
                unsigned w[4] = { c4[q].x, c4[q].y, c4[q].z, c4[q].w };
#pragma unroll
                for (int wq = 0; wq < 4; wq++) {
                    float2 c = __half22float2(*(__half2*)&w[wq]);
                    float2 a = *(float2*)&acc[q * 4 + wq];
                    a.x += c.x; a.y += c.y;
                    acc[q * 4 + wq] = *(u64*)&a;
                }
                if (t + 1 < LC) {
                    const uint4* src = (const uint4*)(g_c16
                        + ((size_t)(l0 + t + 1) * Bsz + b0 + b) * Hsz + h0 + shf * 64);
                    c4[q] = src[q];
                }
            }

            if (t + 1 < LC) {
                unsigned* hsn = hsb + nxt * HBUF;
#pragma unroll
                for (int j2 = 0; j2 < 32; j2++) {
                    float2 v = *(float2*)&acc[j2];
                    __half2 h2v = __floats2half2_rn(fmaxf(v.x, 0.0f), fmaxf(v.y, 0.0f));
                    hsn[hcol + j2] = *(unsigned*)&h2v;
                }
            }
            barrier0();
        }
    }
}

// ---------------------------------------------------------------------------
// k_reduce: sum slices + output biases. g_part layout [s][l*B + b][40].
// ---------------------------------------------------------------------------
__global__ void __launch_bounds__(280) k_reduce(const float* __restrict__ bmu,
                                                const float* __restrict__ bsg,
                                                const float* __restrict__ bpi,
                                                float* __restrict__ out)
{
    const int p = threadIdx.x / 35;
    const int j = threadIdx.x % 35;
    const size_t pr = (size_t)blockIdx.x * 8 + p;
    const int l = (int)(pr >> 8);
    const int b = (int)(pr & 255);

    float v = 0.0f;
#pragma unroll
    for (int s = 0; s < NSL; s++)
        v += g_part[((size_t)s * BL + pr) * 40 + j];

    float bias;
    if (j < 15)      bias = bmu[l * Osz + j];
    else if (j < 30) bias = bsg[l * Osz + (j - 15)];
    else             bias = bpi[l * Msz + (j - 30)];

    out[((size_t)b * Lsz + l) * Jsz + j] = v + bias;
}

// ---------------------------------------------------------------------------
extern "C" void kernel_launch(void* const* d_in, const int* in_sizes, int n_in,
                              void* d_out, int out_size)
{
    const float* inp  = (const float*)d_in[0];
    const float* zz   = (const float*)d_in[1];
    const float* W    = (const float*)d_in[2];
    const float* benc = (const float*)d_in[3];
    const float* Vmu  = (const float*)d_in[4];
    const float* bmu  = (const float*)d_in[5];
    const float* Vsg  = (const float*)d_in[6];
    const float* bsg  = (const float*)d_in[7];
    const float* Vpi  = (const float*)d_in[8];
    const float* bpi  = (const float*)d_in[9];
    float* out = (float*)d_out;

    cudaFuncSetAttribute(k_sums, cudaFuncAttributeMaxDynamicSharedMemorySize, SMS_TOT);
    cudaFuncSetAttribute(k_all,  cudaFuncAttributeMaxDynamicSharedMemorySize, SMA_TOT);

    k_sums<<<dim3(NBT * NSL, NC), NT, SMS_TOT>>>(inp, zz, W);
    k_scan<<<BH / 256, 256>>>(benc);
    k_all <<<dim3(NBT * NSL, NC), NT, SMA_TOT>>>(Vmu, Vsg, Vpi);
    k_reduce<<<BL / 8, 280>>>(bmu, bsg, bpi, out);
}

// round 16
// speedup vs baseline: 1.2554x; 1.2554x over previous
#include <cuda_runtime.h>
#include <cuda_fp16.h>
#include <cstdint>

#define Bsz 256
#define Lsz 500
#define Dsz 3
#define Csz 32
#define Isz 35
#define Hsz 512
#define Msz 5
#define Osz 15
#define Jsz 35
#define NC  50
#define LC  10
#define BH  (Bsz*Hsz)   /* 131072 */
#define BL  (Bsz*Lsz)   /* 128000 */
#define NSL 4           /* h slices */
#define HS  (Hsz/NSL)   /* 128 */
#define BT  128         /* b tile */
#define NBT (Bsz/BT)    /* 2 */
#define XP  44          /* xs row stride (floats), k_sums */
#define NT  512

#define WCNT (Isz*HS)   /* 4480 */
#define XCNT (BT*XP)    /* 5632 */

/* k_all v4 smem (R14 known-good): hs[2][128][68] u32 + vs[2][64][40] u32 */
#define HROW 68
#define HBUF (128*HROW)
#define VBUF (64*40)
#define SM_HS 0
#define SM_VS (2*HBUF*4)
#define SMA_TOT (SM_VS + 2*VBUF*4)   /* 90112 B */

extern __shared__ __align__(16) char dyn_smem[];

// Scratch
__device__ __align__(16) float  g_S[(size_t)NC * BH];
__device__ __align__(16) float  g_P[(size_t)NC * BH];
__device__ __align__(16) __half g_part[(size_t)NSL * BL * 40];   // fp16 partials (41 MB)
__device__ __align__(16) __half g_c16[(size_t)Lsz * BH];

using u64 = unsigned long long;

__device__ __forceinline__ u64 splat2(float x) {
    u64 r; unsigned u = __float_as_uint(x);
    asm("mov.b64 %0, {%1, %1};" : "=l"(r) : "r"(u));
    return r;
}
__device__ __forceinline__ u64 fma2(u64 a, u64 b, u64 c) {
    u64 d; asm("fma.rn.f32x2 %0, %1, %2, %3;" : "=l"(d) : "l"(a), "l"(b), "l"(c));
    return d;
}
__device__ __forceinline__ u64 add2(u64 a, u64 b) {
    u64 d; asm("add.rn.f32x2 %0, %1, %2;" : "=l"(d) : "l"(a), "l"(b));
    return d;
}
__device__ __forceinline__ void cp16(unsigned dst, const void* src) {
    asm volatile("cp.async.ca.shared.global [%0], [%1], 16;" :: "r"(dst), "l"(src));
}
__device__ __forceinline__ void cp4(unsigned dst, const void* src) {
    asm volatile("cp.async.ca.shared.global [%0], [%1], 4;" :: "r"(dst), "l"(src));
}
__device__ __forceinline__ void cp_commit() { asm volatile("cp.async.commit_group;"); }
__device__ __forceinline__ void cp_wait0()  { asm volatile("cp.async.wait_group 0;"); }
__device__ __forceinline__ void barrier0()  { asm volatile("barrier.sync 0;" ::: "memory"); }

// m16n8k16 fp16 HMMA, fp32 accumulate (fragment layout validated R10/R11/R14)
__device__ __forceinline__ void mma_f16(float d[4],
                                        unsigned a0, unsigned a1, unsigned a2, unsigned a3,
                                        unsigned b0, unsigned b1) {
    asm volatile(
        "mma.sync.aligned.m16n8k16.row.col.f32.f16.f16.f32 "
        "{%0,%1,%2,%3}, {%4,%5,%6,%7}, {%8,%9}, {%0,%1,%2,%3};"
        : "+f"(d[0]), "+f"(d[1]), "+f"(d[2]), "+f"(d[3])
        : "r"(a0), "r"(a1), "r"(a2), "r"(a3), "r"(b0), "r"(b1));
}

// ---------------------------------------------------------------------------
// k_sums: R10 known-good (153us) + skip dead c16 store at t == LC-1.
// ---------------------------------------------------------------------------
__device__ __forceinline__ void stage_wx_async(unsigned ws_a, unsigned xs_a,
                                               const float* __restrict__ W,
                                               const float* __restrict__ inp,
                                               const float* __restrict__ zz,
                                               int l, int h0, int b0, int tid)
{
    const float4* wsrc = (const float4*)(W + (size_t)l * (Isz * Hsz)) + (h0 >> 2);
#pragma unroll
    for (int q = 0; q < 3; q++) {
        int idx = tid + NT * q;
        if (idx < Isz * 32) {
            int row = idx >> 5, col = idx & 31;
            cp16(ws_a + (unsigned)(row * 32 + col) * 16, wsrc + row * 128 + col);
        }
    }
#pragma unroll
    for (int q = 0; q < 2; q++) {
        int idx = tid + NT * q;
        int b = idx >> 3, qf = idx & 7;
        cp16(xs_a + (unsigned)(b * XP + 4 + qf * 4) * 4,
             zz + (size_t)(b0 + b) * (Lsz * Csz) + (size_t)l * Csz + qf * 4);
    }
    if (tid < BT * Dsz) {
        int b = tid / Dsz, i = tid % Dsz;
        cp4(xs_a + (unsigned)(b * XP + i) * 4,
            inp + (size_t)(b0 + b) * (Lsz * Dsz) + (size_t)l * Dsz + i);
    }
}

__device__ __forceinline__ void encode_step(u64 c2[4][4], const float* ws,
                                            const float* xs, int bg, int hg)
{
#pragma unroll
    for (int r = 0; r < 4; r++)
#pragma unroll
        for (int p = 0; p < 4; p++) c2[r][p] = 0ull;
#pragma unroll
    for (int i = 0; i < Isz; i++) {
        const int xc = (i < Dsz) ? i : i + 1;
        u64 xa[4], wv[4];
#pragma unroll
        for (int r = 0; r < 4; r++) xa[r] = splat2(xs[(bg * 4 + r) * XP + xc]);
#pragma unroll
        for (int p = 0; p < 4; p++) wv[p] = *(const u64*)&ws[i * HS + hg * 2 + 32 * p];
#pragma unroll
        for (int r = 0; r < 4; r++)
#pragma unroll
            for (int p = 0; p < 4; p++) c2[r][p] = fma2(xa[r], wv[p], c2[r][p]);
    }
}

__global__ void __launch_bounds__(NT) k_sums(const float* __restrict__ inp,
                                             const float* __restrict__ zz,
                                             const float* __restrict__ W)
{
    float* smem = (float*)dyn_smem;
    float* ws[2] = { smem, smem + WCNT };
    float* xs[2] = { smem + 2 * WCNT, smem + 2 * WCNT + XCNT };
    const unsigned sbase = (unsigned)__cvta_generic_to_shared(dyn_smem);
    const unsigned ws_a[2] = { sbase, sbase + WCNT * 4u };
    const unsigned xs_a[2] = { sbase + 2u * WCNT * 4u, sbase + (2u * WCNT + XCNT) * 4u };

    const int tid = threadIdx.x;
    const int b0  = (blockIdx.x / NSL) * BT;
    const int h0  = (blockIdx.x % NSL) * HS;
    const int k   = blockIdx.y;
    const int bg  = tid >> 4, hg = tid & 15;

    u64 acc[4][4];
#pragma unroll
    for (int r = 0; r < 4; r++)
#pragma unroll
        for (int p = 0; p < 4; p++) acc[r][p] = 0ull;

    stage_wx_async(ws_a[0], xs_a[0], W, inp, zz, k * LC, h0, b0, tid);
    cp_commit(); cp_wait0();
    __syncthreads();

    for (int t = 0; t < LC; t++) {
        const int l = k * LC + t;
        const int cur = t & 1, nxt = cur ^ 1;
        if (t + 1 < LC) {
            stage_wx_async(ws_a[nxt], xs_a[nxt], W, inp, zz, l + 1, h0, b0, tid);
            cp_commit();
        }
        u64 c2[4][4];
        encode_step(c2, ws[cur], xs[cur], bg, hg);
        if (t + 1 < LC) {
            // c16[l] with l = chunk-last is never consumed -> skip that store
#pragma unroll
            for (int r = 0; r < 4; r++) {
                __half* crow = g_c16 + ((size_t)l * Bsz + b0 + bg * 4 + r) * Hsz + h0;
#pragma unroll
                for (int p = 0; p < 4; p++) {
                    acc[r][p] = add2(acc[r][p], c2[r][p]);
                    float2 f = *(float2*)&c2[r][p];
                    *(__half2*)&crow[hg * 2 + 32 * p] = __floats2half2_rn(f.x, f.y);
                }
            }
        } else {
#pragma unroll
            for (int r = 0; r < 4; r++)
#pragma unroll
                for (int p = 0; p < 4; p++) acc[r][p] = add2(acc[r][p], c2[r][p]);
        }
        cp_wait0();
        __syncthreads();
    }

    float* sb = g_S + (size_t)k * BH + (size_t)b0 * Hsz + h0;
#pragma unroll
    for (int r = 0; r < 4; r++)
#pragma unroll
        for (int p = 0; p < 4; p++)
            *(u64*)&sb[(size_t)(bg * 4 + r) * Hsz + hg * 2 + 32 * p] = acc[r][p];
}

__global__ void k_scan(const float* __restrict__ benc)
{
    const int idx = blockIdx.x * 256 + threadIdx.x;
    float run = benc[idx & (Hsz - 1)];
#pragma unroll 5
    for (int k = 0; k < NC; k++) {
        g_P[(size_t)k * BH + idx] = run;
        run += g_S[(size_t)k * BH + idx];
    }
}

// ---------------------------------------------------------------------------
// k_all v4 (R14): warp-specialized. fp16 g_part stores; dead c16 load skipped.
// ---------------------------------------------------------------------------
__global__ void __launch_bounds__(NT) k_all(const float* __restrict__ Vmu,
                                            const float* __restrict__ Vsg,
                                            const float* __restrict__ Vpi)
{
    unsigned* hsb = (unsigned*)(dyn_smem + SM_HS);   // [2][128][HROW]
    unsigned* vsb = (unsigned*)(dyn_smem + SM_VS);   // [2][64][40]

    const int tid = threadIdx.x;
    const int wid = tid >> 5, lane = tid & 31;
    const int b0  = (blockIdx.x / NSL) * BT;
    const int s   = blockIdx.x % NSL;
    const int h0  = s * HS;
    const int l0  = blockIdx.y * LC;

    if (wid < 8) {
        // ================= MMA role =================
        const int sb = wid;
        const int rq = lane >> 2, kl = lane & 3;
        const int rb = sb * 16 + rq;

        unsigned vq[10], vdst[10];
#pragma unroll
        for (int q = 0; q < 10; q++) {
            int u = tid + 256 * q;
            int h2 = u / 40, jc = u % 40;
            unsigned tag, off;
            if (jc < 15)      { tag = 0u; off = (h0 + 2 * h2) * Osz + jc; }
            else if (jc < 30) { tag = 1u; off = (h0 + 2 * h2) * Osz + (jc - 15); }
            else if (jc < 35) { tag = 2u; off = (h0 + 2 * h2) * Msz + (jc - 30); }
            else              { tag = 3u; off = 0; }
            vq[q] = (tag << 30) | off;
            vdst[q] = (unsigned)(h2 * 40 + jc);
        }
        auto load_V = [&](int l, unsigned vreg[10]) {
            const size_t lmu = (size_t)l * (Hsz * Osz);
            const size_t lpi = (size_t)l * (Hsz * Msz);
#pragma unroll
            for (int q = 0; q < 10; q++) {
                unsigned tag = vq[q] >> 30, off = vq[q] & 0x3FFFFFFFu;
                float v0 = 0.0f, v1 = 0.0f;
                if (tag == 0u)      { v0 = Vmu[lmu + off]; v1 = Vmu[lmu + off + Osz]; }
                else if (tag == 1u) { v0 = Vsg[lmu + off]; v1 = Vsg[lmu + off + Osz]; }
                else if (tag == 2u) { v0 = Vpi[lpi + off]; v1 = Vpi[lpi + off + Msz]; }
                __half2 h2v = __floats2half2_rn(v0, v1);
                vreg[q] = *(unsigned*)&h2v;
            }
        };

        {
            unsigned v0[10];
            load_V(l0, v0);
#pragma unroll
            for (int q = 0; q < 10; q++) vsb[vdst[q]] = v0[q];
        }
        barrier0();

        for (int t = 0; t < LC; t++) {
            const int l = l0 + t;
            const int cur = t & 1, nxt = cur ^ 1;
            const unsigned* hsc = hsb + cur * HBUF;
            const unsigned* vsc = vsb + cur * VBUF;

            unsigned vreg[10];
            if (t + 1 < LC) load_V(l + 1, vreg);

            float d[5][4];
#pragma unroll
            for (int n = 0; n < 5; n++)
#pragma unroll
                for (int u = 0; u < 4; u++) d[n][u] = 0.0f;

#pragma unroll
            for (int kc = 0; kc < 8; kc++) {
                const int k0h = kc * 8;
                unsigned a0 = hsc[rb * HROW + k0h + kl];
                unsigned a1 = hsc[(rb + 8) * HROW + k0h + kl];
                unsigned a2 = hsc[rb * HROW + k0h + 4 + kl];
                unsigned a3 = hsc[(rb + 8) * HROW + k0h + 4 + kl];
#pragma unroll
                for (int n = 0; n < 5; n++) {
                    unsigned bf0 = vsc[(k0h + kl) * 40 + n * 8 + rq];
                    unsigned bf1 = vsc[(k0h + 4 + kl) * 40 + n * 8 + rq];
                    mma_f16(d[n], a0, a1, a2, a3, bf0, bf1);
                }
            }

            // store fp16 partials
            {
                __half* d0 = g_part + ((size_t)s * BL + (size_t)l * Bsz + (b0 + rb)) * 40;
                __half* d1 = g_part + ((size_t)s * BL + (size_t)l * Bsz + (b0 + rb + 8)) * 40;
#pragma unroll
                for (int n = 0; n < 5; n++) {
                    const int j = n * 8 + 2 * kl;
                    *(__half2*)&d0[j] = __floats2half2_rn(d[n][0], d[n][1]);
                    *(__half2*)&d1[j] = __floats2half2_rn(d[n][2], d[n][3]);
                }
            }

            if (t + 1 < LC) {
                unsigned* vsn = vsb + nxt * VBUF;
#pragma unroll
                for (int q = 0; q < 10; q++) vsn[vdst[q]] = vreg[q];
            }
            barrier0();
        }
    } else {
        // ================= STATE role =================
        const int stid = tid - 256;
        const int b    = stid >> 1;
        const int shf  = stid & 1;
        const unsigned hcol = (unsigned)(b * HROW + shf * 32);

        u64 acc[32];
        {
            const float* P = g_P + (size_t)blockIdx.y * BH
                           + (size_t)(b0 + b) * Hsz + h0 + shf * 64;
#pragma unroll
            for (int j2 = 0; j2 < 32; j2++) {
                float2 v = *(const float2*)&P[2 * j2];
                acc[j2] = *(const u64*)&v;
            }
        }
        {
            unsigned* hsn = hsb;
#pragma unroll
            for (int j2 = 0; j2 < 32; j2++) {
                float2 v = *(float2*)&acc[j2];
                __half2 h2v = __floats2half2_rn(fmaxf(v.x, 0.0f), fmaxf(v.y, 0.0f));
                hsn[hcol + j2] = *(unsigned*)&h2v;
            }
        }
        uint4 c4[8];
        {
            const uint4* src = (const uint4*)(g_c16
                + ((size_t)l0 * Bsz + b0 + b) * Hsz + h0 + shf * 64);
#pragma unroll
            for (int q = 0; q < 8; q++) c4[q] = src[q];
        }
        barrier0();

        for (int t = 0; t < LC; t++) {
            const int nxt = (t & 1) ^ 1;

            if (t + 1 < LC) {
                // consume c16[l0+t]; prefetch c16[l0+t+1] only if it will be consumed
#pragma unroll
                for (int q = 0; q < 8; q++) {
                    unsigned w[4] = { c4[q].x, c4[q].y, c4[q].z, c4[q].w };
#pragma unroll
                    for (int wq = 0; wq < 4; wq++) {
                        float2 c = __half22float2(*(__half2*)&w[wq]);
                        float2 a = *(float2*)&acc[q * 4 + wq];
                        a.x += c.x; a.y += c.y;
                        acc[q * 4 + wq] = *(u64*)&a;
                    }
                    if (t + 2 < LC) {
                        const uint4* src = (const uint4*)(g_c16
                            + ((size_t)(l0 + t + 1) * Bsz + b0 + b) * Hsz + h0 + shf * 64);
                        c4[q] = src[q];
                    }
                }
                // publish relu(a[l+1]) -> hs[nxt]
                unsigned* hsn = hsb + nxt * HBUF;
#pragma unroll
                for (int j2 = 0; j2 < 32; j2++) {
                    float2 v = *(float2*)&acc[j2];
                    __half2 h2v = __floats2half2_rn(fmaxf(v.x, 0.0f), fmaxf(v.y, 0.0f));
                    hsn[hcol + j2] = *(unsigned*)&h2v;
                }
            }
            // final step: acc update is dead (chunk boundary) -> skip entirely
            barrier0();
        }
    }
}

// ---------------------------------------------------------------------------
// k_reduce: sum fp16 slices + output biases. g_part layout [s][l*B + b][40].
// ---------------------------------------------------------------------------
__global__ void __launch_bounds__(280) k_reduce(const float* __restrict__ bmu,
                                                const float* __restrict__ bsg,
                                                const float* __restrict__ bpi,
                                                float* __restrict__ out)
{
    const int p = threadIdx.x / 35;
    const int j = threadIdx.x % 35;
    const size_t pr = (size_t)blockIdx.x * 8 + p;
    const int l = (int)(pr >> 8);
    const int b = (int)(pr & 255);

    float v = 0.0f;
#pragma unroll
    for (int s = 0; s < NSL; s++)
        v += __half2float(g_part[((size_t)s * BL + pr) * 40 + j]);

    float bias;
    if (j < 15)      bias = bmu[l * Osz + j];
    else if (j < 30) bias = bsg[l * Osz + (j - 15)];
    else             bias = bpi[l * Msz + (j - 30)];

    out[((size_t)b * Lsz + l) * Jsz + j] = v + bias;
}

// ---------------------------------------------------------------------------
extern "C" void kernel_launch(void* const* d_in, const int* in_sizes, int n_in,
                              void* d_out, int out_size)
{
    const float* inp  = (const float*)d_in[0];
    const float* zz   = (const float*)d_in[1];
    const float* W    = (const float*)d_in[2];
    const float* benc = (const float*)d_in[3];
    const float* Vmu  = (const float*)d_in[4];
    const float* bmu  = (const float*)d_in[5];
    const float* Vsg  = (const float*)d_in[6];
    const float* bsg  = (const float*)d_in[7];
    const float* Vpi  = (const float*)d_in[8];
    const float* bpi  = (const float*)d_in[9];
    float* out = (float*)d_out;

    const int sm1 = (2 * WCNT + 2 * XCNT) * (int)sizeof(float);   // 80.9 KB
    cudaFuncSetAttribute(k_sums, cudaFuncAttributeMaxDynamicSharedMemorySize, sm1);
    cudaFuncSetAttribute(k_all,  cudaFuncAttributeMaxDynamicSharedMemorySize, SMA_TOT);

    k_sums<<<dim3(NBT * NSL, NC), NT, sm1>>>(inp, zz, W);
    k_scan<<<BH / 256, 256>>>(benc);
    k_all <<<dim3(NBT * NSL, NC), NT, SMA_TOT>>>(Vmu, Vsg, Vpi);
    k_reduce<<<BL / 8, 280>>>(bmu, bsg, bpi, out);
}

// round 17
// speedup vs baseline: 1.7609x; 1.4027x over previous
#include <cuda_runtime.h>
#include <cuda_fp16.h>
#include <cstdint>

#define Bsz 256
#define Lsz 500
#define Dsz 3
#define Csz 32
#define Isz 35
#define Hsz 512
#define Msz 5
#define Osz 15
#define Jsz 35
#define NC  50
#define LC  10
#define BH  (Bsz*Hsz)   /* 131072 */
#define BL  (Bsz*Lsz)   /* 128000 */
#define NSL 4           /* h slices */
#define HS  (Hsz/NSL)   /* 128 */
#define BT  128         /* b tile */
#define NBT (Bsz/BT)    /* 2 */
#define XP  44          /* xs row stride (floats), k_sums */
#define NT  512
#define VL  10240       /* packed-V u32 per l (256 h2 x 40) */

#define WCNT (Isz*HS)   /* 4480 */
#define XCNT (BT*XP)    /* 5632 */

/* k_all v4 smem: hs[2][128][68] u32 + vs[2][64][40] u32 */
#define HROW 68
#define HBUF (128*HROW)
#define VBUF (64*40)
#define SM_HS 0
#define SM_VS (2*HBUF*4)
#define SMA_TOT (SM_VS + 2*VBUF*4)   /* 90112 B */

extern __shared__ __align__(16) char dyn_smem[];

// Scratch
__device__ __align__(16) float    g_S[(size_t)NC * BH];
__device__ __align__(16) float    g_P[(size_t)NC * BH];
__device__ __align__(16) __half   g_part[(size_t)NSL * BL * 40];   // fp16 partials
__device__ __align__(16) __half   g_c16[(size_t)Lsz * BH];
__device__ __align__(16) unsigned g_V16[(size_t)Lsz * VL];         // packed V half2 (20.5 MB)

using u64 = unsigned long long;

__device__ __forceinline__ u64 splat2(float x) {
    u64 r; unsigned u = __float_as_uint(x);
    asm("mov.b64 %0, {%1, %1};" : "=l"(r) : "r"(u));
    return r;
}
__device__ __forceinline__ u64 fma2(u64 a, u64 b, u64 c) {
    u64 d; asm("fma.rn.f32x2 %0, %1, %2, %3;" : "=l"(d) : "l"(a), "l"(b), "l"(c));
    return d;
}
__device__ __forceinline__ u64 add2(u64 a, u64 b) {
    u64 d; asm("add.rn.f32x2 %0, %1, %2;" : "=l"(d) : "l"(a), "l"(b));
    return d;
}
__device__ __forceinline__ void cp16(unsigned dst, const void* src) {
    asm volatile("cp.async.ca.shared.global [%0], [%1], 16;" :: "r"(dst), "l"(src));
}
__device__ __forceinline__ void cp4(unsigned dst, const void* src) {
    asm volatile("cp.async.ca.shared.global [%0], [%1], 4;" :: "r"(dst), "l"(src));
}
__device__ __forceinline__ void cp_commit() { asm volatile("cp.async.commit_group;"); }
__device__ __forceinline__ void cp_wait0()  { asm volatile("cp.async.wait_group 0;"); }
__device__ __forceinline__ void barrier0()  { asm volatile("barrier.sync 0;" ::: "memory"); }

// m16n8k16 fp16 HMMA, fp32 accumulate (fragment layout validated R10/R11/R14)
__device__ __forceinline__ void mma_f16(float d[4],
                                        unsigned a0, unsigned a1, unsigned a2, unsigned a3,
                                        unsigned b0, unsigned b1) {
    asm volatile(
        "mma.sync.aligned.m16n8k16.row.col.f32.f16.f16.f32 "
        "{%0,%1,%2,%3}, {%4,%5,%6,%7}, {%8,%9}, {%0,%1,%2,%3};"
        : "+f"(d[0]), "+f"(d[1]), "+f"(d[2]), "+f"(d[3])
        : "r"(a0), "r"(a1), "r"(a2), "r"(a3), "r"(b0), "r"(b1));
}

// ---------------------------------------------------------------------------
// k_packV: one-time pack V_mu|V_sigma|V_pi -> g_V16[l][h2 0..255][jc 0..39]
// (half2 over h, zero-padded jc>=35). Same fp16 rounding as the old staging.
// ---------------------------------------------------------------------------
__global__ void __launch_bounds__(NT) k_packV(const float* __restrict__ Vmu,
                                              const float* __restrict__ Vsg,
                                              const float* __restrict__ Vpi)
{
    const int l = blockIdx.x;
    const size_t lmu = (size_t)l * (Hsz * Osz);
    const size_t lpi = (size_t)l * (Hsz * Msz);
    unsigned* dst = g_V16 + (size_t)l * VL;
    for (int u = threadIdx.x; u < VL; u += NT) {
        int h2 = u / 40, jc = u % 40;
        int h = 2 * h2;
        float v0 = 0.0f, v1 = 0.0f;
        if (jc < 15)      { v0 = Vmu[lmu + h * Osz + jc];        v1 = Vmu[lmu + (h + 1) * Osz + jc]; }
        else if (jc < 30) { v0 = Vsg[lmu + h * Osz + (jc - 15)]; v1 = Vsg[lmu + (h + 1) * Osz + (jc - 15)]; }
        else if (jc < 35) { v0 = Vpi[lpi + h * Msz + (jc - 30)]; v1 = Vpi[lpi + (h + 1) * Msz + (jc - 30)]; }
        __half2 h2v = __floats2half2_rn(v0, v1);
        dst[u] = *(unsigned*)&h2v;
    }
}

// ---------------------------------------------------------------------------
// k_sums: R16 known-good (R10 shape + dead-store skip).
// ---------------------------------------------------------------------------
__device__ __forceinline__ void stage_wx_async(unsigned ws_a, unsigned xs_a,
                                               const float* __restrict__ W,
                                               const float* __restrict__ inp,
                                               const float* __restrict__ zz,
                                               int l, int h0, int b0, int tid)
{
    const float4* wsrc = (const float4*)(W + (size_t)l * (Isz * Hsz)) + (h0 >> 2);
#pragma unroll
    for (int q = 0; q < 3; q++) {
        int idx = tid + NT * q;
        if (idx < Isz * 32) {
            int row = idx >> 5, col = idx & 31;
            cp16(ws_a + (unsigned)(row * 32 + col) * 16, wsrc + row * 128 + col);
        }
    }
#pragma unroll
    for (int q = 0; q < 2; q++) {
        int idx = tid + NT * q;
        int b = idx >> 3, qf = idx & 7;
        cp16(xs_a + (unsigned)(b * XP + 4 + qf * 4) * 4,
             zz + (size_t)(b0 + b) * (Lsz * Csz) + (size_t)l * Csz + qf * 4);
    }
    if (tid < BT * Dsz) {
        int b = tid / Dsz, i = tid % Dsz;
        cp4(xs_a + (unsigned)(b * XP + i) * 4,
            inp + (size_t)(b0 + b) * (Lsz * Dsz) + (size_t)l * Dsz + i);
    }
}

__device__ __forceinline__ void encode_step(u64 c2[4][4], const float* ws,
                                            const float* xs, int bg, int hg)
{
#pragma unroll
    for (int r = 0; r < 4; r++)
#pragma unroll
        for (int p = 0; p < 4; p++) c2[r][p] = 0ull;
#pragma unroll
    for (int i = 0; i < Isz; i++) {
        const int xc = (i < Dsz) ? i : i + 1;
        u64 xa[4], wv[4];
#pragma unroll
        for (int r = 0; r < 4; r++) xa[r] = splat2(xs[(bg * 4 + r) * XP + xc]);
#pragma unroll
        for (int p = 0; p < 4; p++) wv[p] = *(const u64*)&ws[i * HS + hg * 2 + 32 * p];
#pragma unroll
        for (int r = 0; r < 4; r++)
#pragma unroll
            for (int p = 0; p < 4; p++) c2[r][p] = fma2(xa[r], wv[p], c2[r][p]);
    }
}

__global__ void __launch_bounds__(NT) k_sums(const float* __restrict__ inp,
                                             const float* __restrict__ zz,
                                             const float* __restrict__ W)
{
    float* smem = (float*)dyn_smem;
    float* ws[2] = { smem, smem + WCNT };
    float* xs[2] = { smem + 2 * WCNT, smem + 2 * WCNT + XCNT };
    const unsigned sbase = (unsigned)__cvta_generic_to_shared(dyn_smem);
    const unsigned ws_a[2] = { sbase, sbase + WCNT * 4u };
    const unsigned xs_a[2] = { sbase + 2u * WCNT * 4u, sbase + (2u * WCNT + XCNT) * 4u };

    const int tid = threadIdx.x;
    const int b0  = (blockIdx.x / NSL) * BT;
    const int h0  = (blockIdx.x % NSL) * HS;
    const int k   = blockIdx.y;
    const int bg  = tid >> 4, hg = tid & 15;

    u64 acc[4][4];
#pragma unroll
    for (int r = 0; r < 4; r++)
#pragma unroll
        for (int p = 0; p < 4; p++) acc[r][p] = 0ull;

    stage_wx_async(ws_a[0], xs_a[0], W, inp, zz, k * LC, h0, b0, tid);
    cp_commit(); cp_wait0();
    __syncthreads();

    for (int t = 0; t < LC; t++) {
        const int l = k * LC + t;
        const int cur = t & 1, nxt = cur ^ 1;
        if (t + 1 < LC) {
            stage_wx_async(ws_a[nxt], xs_a[nxt], W, inp, zz, l + 1, h0, b0, tid);
            cp_commit();
        }
        u64 c2[4][4];
        encode_step(c2, ws[cur], xs[cur], bg, hg);
        if (t + 1 < LC) {
#pragma unroll
            for (int r = 0; r < 4; r++) {
                __half* crow = g_c16 + ((size_t)l * Bsz + b0 + bg * 4 + r) * Hsz + h0;
#pragma unroll
                for (int p = 0; p < 4; p++) {
                    acc[r][p] = add2(acc[r][p], c2[r][p]);
                    float2 f = *(float2*)&c2[r][p];
                    *(__half2*)&crow[hg * 2 + 32 * p] = __floats2half2_rn(f.x, f.y);
                }
            }
        } else {
#pragma unroll
            for (int r = 0; r < 4; r++)
#pragma unroll
                for (int p = 0; p < 4; p++) acc[r][p] = add2(acc[r][p], c2[r][p]);
        }
        cp_wait0();
        __syncthreads();
    }

    float* sb = g_S + (size_t)k * BH + (size_t)b0 * Hsz + h0;
#pragma unroll
    for (int r = 0; r < 4; r++)
#pragma unroll
        for (int p = 0; p < 4; p++)
            *(u64*)&sb[(size_t)(bg * 4 + r) * Hsz + hg * 2 + 32 * p] = acc[r][p];
}

__global__ void k_scan(const float* __restrict__ benc)
{
    const int idx = blockIdx.x * 256 + threadIdx.x;
    float run = benc[idx & (Hsz - 1)];
#pragma unroll 5
    for (int k = 0; k < NC; k++) {
        g_P[(size_t)k * BH + idx] = run;
        run += g_S[(size_t)k * BH + idx];
    }
}

// ---------------------------------------------------------------------------
// k_all v5: R16 structure; V staged via cp.async from packed g_V16.
// ---------------------------------------------------------------------------
__global__ void __launch_bounds__(NT) k_all()
{
    unsigned* hsb = (unsigned*)(dyn_smem + SM_HS);   // [2][128][HROW]
    unsigned* vsb = (unsigned*)(dyn_smem + SM_VS);   // [2][64][40]
    const unsigned sbase = (unsigned)__cvta_generic_to_shared(dyn_smem);
    const unsigned vs_a[2] = { sbase + SM_VS, sbase + SM_VS + VBUF * 4u };

    const int tid = threadIdx.x;
    const int wid = tid >> 5, lane = tid & 31;
    const int b0  = (blockIdx.x / NSL) * BT;
    const int s   = blockIdx.x % NSL;
    const int h0  = s * HS;
    const int l0  = blockIdx.y * LC;

    if (wid < 8) {
        // ================= MMA role =================
        const int sb = wid;
        const int rq = lane >> 2, kl = lane & 3;
        const int rb = sb * 16 + rq;

        // stage packed V slice: 64 rows x 40 u32 = 640 16B-chunks
        auto stage_V = [&](int l, unsigned va) {
            const unsigned* src = g_V16 + (size_t)l * VL + (size_t)(s * 64) * 40;
#pragma unroll
            for (int q = 0; q < 3; q++) {
                int idx = tid + 256 * q;
                if (idx < 640) cp16(va + (unsigned)idx * 16, src + idx * 4);
            }
            cp_commit();
        };

        stage_V(l0, vs_a[0]);
        cp_wait0();
        barrier0();

        for (int t = 0; t < LC; t++) {
            const int l = l0 + t;
            const int cur = t & 1, nxt = cur ^ 1;
            const unsigned* hsc = hsb + cur * HBUF;
            const unsigned* vsc = vsb + cur * VBUF;

            if (t + 1 < LC) stage_V(l + 1, vs_a[nxt]);

            float d[5][4];
#pragma unroll
            for (int n = 0; n < 5; n++)
#pragma unroll
                for (int u = 0; u < 4; u++) d[n][u] = 0.0f;

#pragma unroll
            for (int kc = 0; kc < 8; kc++) {
                const int k0h = kc * 8;
                unsigned a0 = hsc[rb * HROW + k0h + kl];
                unsigned a1 = hsc[(rb + 8) * HROW + k0h + kl];
                unsigned a2 = hsc[rb * HROW + k0h + 4 + kl];
                unsigned a3 = hsc[(rb + 8) * HROW + k0h + 4 + kl];
#pragma unroll
                for (int n = 0; n < 5; n++) {
                    unsigned bf0 = vsc[(k0h + kl) * 40 + n * 8 + rq];
                    unsigned bf1 = vsc[(k0h + 4 + kl) * 40 + n * 8 + rq];
                    mma_f16(d[n], a0, a1, a2, a3, bf0, bf1);
                }
            }

            // store fp16 partials
            {
                __half* d0 = g_part + ((size_t)s * BL + (size_t)l * Bsz + (b0 + rb)) * 40;
                __half* d1 = g_part + ((size_t)s * BL + (size_t)l * Bsz + (b0 + rb + 8)) * 40;
#pragma unroll
                for (int n = 0; n < 5; n++) {
                    const int j = n * 8 + 2 * kl;
                    *(__half2*)&d0[j] = __floats2half2_rn(d[n][0], d[n][1]);
                    *(__half2*)&d1[j] = __floats2half2_rn(d[n][2], d[n][3]);
                }
            }

            if (t + 1 < LC) cp_wait0();
            barrier0();
        }
    } else {
        // ================= STATE role (R16 known-good) =================
        const int stid = tid - 256;
        const int b    = stid >> 1;
        const int shf  = stid & 1;
        const unsigned hcol = (unsigned)(b * HROW + shf * 32);

        u64 acc[32];
        {
            const float* P = g_P + (size_t)blockIdx.y * BH
                           + (size_t)(b0 + b) * Hsz + h0 + shf * 64;
#pragma unroll
            for (int j2 = 0; j2 < 32; j2++) {
                float2 v = *(const float2*)&P[2 * j2];
                acc[j2] = *(const u64*)&v;
            }
        }
        {
            unsigned* hsn = hsb;
#pragma unroll
            for (int j2 = 0; j2 < 32; j2++) {
                float2 v = *(float2*)&acc[j2];
                __half2 h2v = __floats2half2_rn(fmaxf(v.x, 0.0f), fmaxf(v.y, 0.0f));
                hsn[hcol + j2] = *(unsigned*)&h2v;
            }
        }
        uint4 c4[8];
        {
            const uint4* src = (const uint4*)(g_c16
                + ((size_t)l0 * Bsz + b0 + b) * Hsz + h0 + shf * 64);
#pragma unroll
            for (int q = 0; q < 8; q++) c4[q] = src[q];
        }
        barrier0();

        for (int t = 0; t < LC; t++) {
            const int nxt = (t & 1) ^ 1;

            if (t + 1 < LC) {
#pragma unroll
                for (int q = 0; q < 8; q++) {
                    unsigned w[4] = { c4[q].x, c4[q].y, c4[q].z, c4[q].w };
#pragma unroll
                    for (int wq = 0; wq < 4; wq++) {
                        float2 c = __half22float2(*(__half2*)&w[wq]);
                        float2 a = *(float2*)&acc[q * 4 + wq];
                        a.x += c.x; a.y += c.y;
                        acc[q * 4 + wq] = *(u64*)&a;
                    }
                    if (t + 2 < LC) {
                        const uint4* src = (const uint4*)(g_c16
                            + ((size_t)(l0 + t + 1) * Bsz + b0 + b) * Hsz + h0 + shf * 64);
                        c4[q] = src[q];
                    }
                }
                unsigned* hsn = hsb + nxt * HBUF;
#pragma unroll
                for (int j2 = 0; j2 < 32; j2++) {
                    float2 v = *(float2*)&acc[j2];
                    __half2 h2v = __floats2half2_rn(fmaxf(v.x, 0.0f), fmaxf(v.y, 0.0f));
                    hsn[hcol + j2] = *(unsigned*)&h2v;
                }
            }
            barrier0();
        }
    }
}

// ---------------------------------------------------------------------------
// k_reduce v2: half2-vectorized. 160 threads = 8 (b,l) pairs x 20 half2-j.
// ---------------------------------------------------------------------------
__global__ void __launch_bounds__(160) k_reduce(const float* __restrict__ bmu,
                                                const float* __restrict__ bsg,
                                                const float* __restrict__ bpi,
                                                float* __restrict__ out)
{
    const int p  = threadIdx.x / 20;
    const int j2 = threadIdx.x % 20;
    const int j  = 2 * j2;
    if (j >= Jsz) return;
    const size_t pr = (size_t)blockIdx.x * 8 + p;
    const int l = (int)(pr >> 8);
    const int b = (int)(pr & 255);

    float v0 = 0.0f, v1 = 0.0f;
#pragma unroll
    for (int s = 0; s < NSL; s++) {
        __half2 h2v = *(const __half2*)&g_part[((size_t)s * BL + pr) * 40 + j];
        float2 f = __half22float2(h2v);
        v0 += f.x; v1 += f.y;
    }

    auto bias = [&](int jj) -> float {
        if (jj < 15) return bmu[l * Osz + jj];
        if (jj < 30) return bsg[l * Osz + (jj - 15)];
        return bpi[l * Msz + (jj - 30)];
    };
    float* o = out + ((size_t)b * Lsz + l) * Jsz;
    o[j] = v0 + bias(j);
    if (j + 1 < Jsz) o[j + 1] = v1 + bias(j + 1);
}

// ---------------------------------------------------------------------------
extern "C" void kernel_launch(void* const* d_in, const int* in_sizes, int n_in,
                              void* d_out, int out_size)
{
    const float* inp  = (const float*)d_in[0];
    const float* zz   = (const float*)d_in[1];
    const float* W    = (const float*)d_in[2];
    const float* benc = (const float*)d_in[3];
    const float* Vmu  = (const float*)d_in[4];
    const float* bmu  = (const float*)d_in[5];
    const float* Vsg  = (const float*)d_in[6];
    const float* bsg  = (const float*)d_in[7];
    const float* Vpi  = (const float*)d_in[8];
    const float* bpi  = (const float*)d_in[9];
    float* out = (float*)d_out;

    const int sm1 = (2 * WCNT + 2 * XCNT) * (int)sizeof(float);   // 80.9 KB
    cudaFuncSetAttribute(k_sums, cudaFuncAttributeMaxDynamicSharedMemorySize, sm1);
    cudaFuncSetAttribute(k_all,  cudaFuncAttributeMaxDynamicSharedMemorySize, SMA_TOT);

    k_packV<<<Lsz, NT>>>(Vmu, Vsg, Vpi);
    k_sums<<<dim3(NBT * NSL, NC), NT, sm1>>>(inp, zz, W);
    k_scan<<<BH / 256, 256>>>(benc);
    k_all <<<dim3(NBT * NSL, NC), NT, SMA_TOT>>>();
    k_reduce<<<BL / 8, 160>>>(bmu, bsg, bpi, out);
}